// round 9
// baseline (speedup 1.0000x reference)
#include <cuda_runtime.h>
#include <cuda_bf16.h>

// Gather3d: x [1, 128, 16, 128, 128] f32, active_indices [128, 2] i32 in [0,112)
// out [128, 128, 18, 16, 16] f32:
//   out[n, c, T, i, j] = (T < 2) ? 0 : x[0, c, T-2, idx_y[n]+i, idx_x[n]+j]
//
// R5: loop-nest reorder for cross-n L2 reuse. Thread index order is
//   v = ((c*18 + T)*128 + n)*64 + i*4 + j4
// so all 128 n-blocks reading the same 64 KB (c,T) input plane execute in 32
// consecutive CTAs -> the plane is DRAM-fetched ~once and reused from L2
// (~2x block overlap + sector-expansion merging). Stores use __stcs so the
// 302 MB write stream doesn't evict read planes from L2.

#define CC   128   // channels
#define TIN  16    // input time
#define TT   18    // output time (TIN + 2 zero pad frames)
#define HW   128   // H == W
#define NN   128   // number of active blocks
#define BH   16    // block h
#define BW4  4     // block w in float4 units (16 floats)

// total output float4s = 128 * 18 * 128 * 16 * 4 = 18,874,368
#define TOTAL_VEC (CC * TT * NN * BH * BW4)
#define THREADS   256

__global__ __launch_bounds__(THREADS) void gather3d_kernel(
    const float* __restrict__ x,
    const int*   __restrict__ idx,
    float*       __restrict__ out)
{
    int v = blockIdx.x * THREADS + threadIdx.x;
    if (v >= TOTAL_VEC) return;

    // v = (((c*TT + T)*NN + n)*BH + i)*BW4 + j4
    int j4  = v & 3;
    int i   = (v >> 2) & 15;
    int rem = v >> 6;          // (c*TT + T)*NN + n
    int n   = rem & (NN - 1);
    int ct  = rem >> 7;        // c*TT + T
    int T   = ct % TT;         // compile-time const -> mul-shift
    int c   = ct / TT;

    float4 val = make_float4(0.f, 0.f, 0.f, 0.f);
    if (T >= 2) {
        int iy = __ldg(&idx[2 * n]);      // tiny, L2/L1 resident
        int ix = __ldg(&idx[2 * n + 1]);
        int h  = iy + i;                  // <= 126 < 128: always in bounds
        int w  = ix + (j4 << 2);          // w+3 <= 126: always in bounds
        const float* src = x + (((c * TIN + (T - 2)) * HW + h) * HW + w);
        val.x = __ldg(src + 0);
        val.y = __ldg(src + 1);
        val.z = __ldg(src + 2);
        val.w = __ldg(src + 3);
    }

    // out float4 index = ((n*CC + c)*TT + T)*64 + i*4 + j4
    // (contiguous per 64-vec chunk -> warp writes 512 B coalesced; chunks are
    //  1 KB-aligned so every written sector is fully covered)
    int o = (((n * CC + c) * TT + T) << 6) + (i << 2) + j4;
    __stcs(reinterpret_cast<float4*>(out) + o, val);
}

extern "C" void kernel_launch(void* const* d_in, const int* in_sizes, int n_in,
                              void* d_out, int out_size) {
    const float* x   = (const float*)d_in[0];
    const int*   idx = (const int*)d_in[1];
    float*       out = (float*)d_out;

    int blocks = (TOTAL_VEC + THREADS - 1) / THREADS;  // 73,728
    gather3d_kernel<<<blocks, THREADS>>>(x, idx, out);
}

// round 10
// speedup vs baseline: 1.2162x; 1.2162x over previous
#include <cuda_runtime.h>
#include <cuda_bf16.h>

// Gather3d: x [1, 128, 16, 128, 128] f32, active_indices [128, 2] i32 in [0,112)
// out [128, 128, 18, 16, 16] f32:
//   out[n, c, T, i, j] = (T < 2) ? 0 : x[0, c, T-2, idx_y[n]+i, idx_x[n]+j]
//
// R9: L1tex-wavefront-optimized mapping.
//   - CTA = one (n, c) pair; 256 threads = the 16x16 (i, j) spatial block.
//     A warp's LDG.32 spans only 2 input rows (vs 8 before) -> ~2-3 L1
//     wavefronts per 128 B loaded instead of ~8. Warp stores are 128 B
//     contiguous, 128 B aligned -> 1 wavefront.
//   - Each thread loops T = 2..17 with constant strides, amortizing all index
//     math; full unroll gives MLP ~16 independent loads.
//   - Grid order: c outer, n inner -> all 128 n-CTAs reading a (c,T) plane are
//     resident together; each 64 KB plane is DRAM-fetched once, L2-reused.
//   - __stcs streaming stores keep the 302 MB write stream out of L2.

#define CC   128   // channels
#define TIN  16    // input time
#define TT   18    // output time (TIN + 2 zero pad frames)
#define HW   128   // H == W
#define NN   128   // number of active blocks
#define BH   16
#define BW   16

__global__ __launch_bounds__(256) void gather3d_kernel(
    const float* __restrict__ x,
    const int*   __restrict__ idx,
    float*       __restrict__ out)
{
    // blockIdx.x = c * NN + n  (n inner for cross-n L2 reuse of (c,T) planes)
    int n = blockIdx.x & (NN - 1);
    int c = blockIdx.x >> 7;

    int j = threadIdx.x & (BW - 1);   // col within block
    int i = threadIdx.x >> 4;         // row within block

    int iy = __ldg(&idx[2 * n]);      // broadcast across CTA
    int ix = __ldg(&idx[2 * n + 1]);

    // input pointer for T=2 (input t=0); stride per T = one plane = 128*128
    const float* src = x + ((c * TIN + 0) * HW + (iy + i)) * HW + (ix + j);
    // output pointer for this (n, c); chunk is TT*256 floats, 1 KB-aligned rows
    float* dst = out + ((n * CC + c) * TT) * (BH * BW) + i * BW + j;

    // T = 0, 1: zero pad frames (d_out is poisoned, must write zeros)
    __stcs(dst, 0.0f);
    __stcs(dst + BH * BW, 0.0f);
    dst += 2 * BH * BW;

#pragma unroll
    for (int t = 0; t < TIN; ++t) {
        float v = __ldg(src + t * (HW * HW));
        __stcs(dst + t * (BH * BW), v);
    }
}

extern "C" void kernel_launch(void* const* d_in, const int* in_sizes, int n_in,
                              void* d_out, int out_size) {
    const float* x   = (const float*)d_in[0];
    const int*   idx = (const int*)d_in[1];
    float*       out = (float*)d_out;

    gather3d_kernel<<<CC * NN, 256>>>(x, idx, out);  // 16384 CTAs
}

// round 11
// speedup vs baseline: 1.2267x; 1.0087x over previous
#include <cuda_runtime.h>
#include <cuda_bf16.h>

// Gather3d: x [1, 128, 16, 128, 128] f32, active_indices [128, 2] i32 in [0,112)
// out [128, 128, 18, 16, 16] f32:
//   out[n, c, T, i, j] = (T < 2) ? 0 : x[0, c, T-2, idx_y[n]+i, idx_x[n]+j]
//
// R9: L1tex-wavefront-optimized mapping.
//   - CTA = one (n, c) pair; 256 threads = the 16x16 (i, j) spatial block.
//     A warp's LDG.32 spans only 2 input rows (vs 8 before) -> ~2-3 L1
//     wavefronts per 128 B loaded instead of ~8. Warp stores are 128 B
//     contiguous, 128 B aligned -> 1 wavefront.
//   - Each thread loops T = 2..17 with constant strides, amortizing all index
//     math; full unroll gives MLP ~16 independent loads.
//   - Grid order: c outer, n inner -> all 128 n-CTAs reading a (c,T) plane are
//     resident together; each 64 KB plane is DRAM-fetched once, L2-reused.
//   - __stcs streaming stores keep the 302 MB write stream out of L2.

#define CC   128   // channels
#define TIN  16    // input time
#define TT   18    // output time (TIN + 2 zero pad frames)
#define HW   128   // H == W
#define NN   128   // number of active blocks
#define BH   16
#define BW   16

__global__ __launch_bounds__(256) void gather3d_kernel(
    const float* __restrict__ x,
    const int*   __restrict__ idx,
    float*       __restrict__ out)
{
    // blockIdx.x = c * NN + n  (n inner for cross-n L2 reuse of (c,T) planes)
    int n = blockIdx.x & (NN - 1);
    int c = blockIdx.x >> 7;

    int j = threadIdx.x & (BW - 1);   // col within block
    int i = threadIdx.x >> 4;         // row within block

    int iy = __ldg(&idx[2 * n]);      // broadcast across CTA
    int ix = __ldg(&idx[2 * n + 1]);

    // input pointer for T=2 (input t=0); stride per T = one plane = 128*128
    const float* src = x + ((c * TIN + 0) * HW + (iy + i)) * HW + (ix + j);
    // output pointer for this (n, c); chunk is TT*256 floats, 1 KB-aligned rows
    float* dst = out + ((n * CC + c) * TT) * (BH * BW) + i * BW + j;

    // T = 0, 1: zero pad frames (d_out is poisoned, must write zeros)
    __stcs(dst, 0.0f);
    __stcs(dst + BH * BW, 0.0f);
    dst += 2 * BH * BW;

#pragma unroll
    for (int t = 0; t < TIN; ++t) {
        float v = __ldg(src + t * (HW * HW));
        __stcs(dst + t * (BH * BW), v);
    }
}

extern "C" void kernel_launch(void* const* d_in, const int* in_sizes, int n_in,
                              void* d_out, int out_size) {
    const float* x   = (const float*)d_in[0];
    const int*   idx = (const int*)d_in[1];
    float*       out = (float*)d_out;

    gather3d_kernel<<<CC * NN, 256>>>(x, idx, out);  // 16384 CTAs
}